// round 2
// baseline (speedup 1.0000x reference)
#include <cuda_runtime.h>

#define LTOT   4096
#define NST    64
#define BSZ    64
#define NCHUNK 128
#define LC     32

// Scratch (__device__ globals — no allocation allowed).
// g_Y[t][row n][col]: col 0..63 = Xloc (batch cols), col 64..127 = Ploc.
__device__ float g_Y [LTOT * 64 * 128];     // 128 MB
__device__ float g_S [NCHUNK * 64 * 128];   // scan ping
__device__ float g_S2[NCHUNK * 64 * 128];   // scan pong

// (64xW) += (64x64 As) @ (64xW Ys); thread owns 4 rows x TN cols.
template<int W, int TN>
__device__ __forceinline__ void gemm64(const float* __restrict__ As,
                                       const float* __restrict__ Ys,
                                       float acc[4][TN], int r0, int c0) {
#pragma unroll 4
  for (int k0 = 0; k0 < 64; k0 += 4) {
    float a[4][4];
#pragma unroll
    for (int i = 0; i < 4; ++i) {
      float4 av = *reinterpret_cast<const float4*>(&As[(r0 + i) * 64 + k0]);
      a[i][0] = av.x; a[i][1] = av.y; a[i][2] = av.z; a[i][3] = av.w;
    }
#pragma unroll
    for (int kk = 0; kk < 4; ++kk) {
      float y[TN];
      if constexpr (TN == 4) {
        float4 yv = *reinterpret_cast<const float4*>(&Ys[(k0 + kk) * W + c0]);
        y[0] = yv.x; y[1] = yv.y; y[2] = yv.z; y[3] = yv.w;
      } else {
        float2 yv = *reinterpret_cast<const float2*>(&Ys[(k0 + kk) * W + c0]);
        y[0] = yv.x; y[1] = yv.y;
      }
#pragma unroll
      for (int i = 0; i < 4; ++i)
#pragma unroll
        for (int j = 0; j < TN; ++j)
          acc[i][j] += a[i][kk] * y[j];
    }
  }
}

// ---------------- Phase 1: per-chunk joint recurrence, store every step ------
__global__ __launch_bounds__(512) void k_phase1(const float* __restrict__ inp,
                                                const float* __restrict__ A,
                                                const float* __restrict__ Bst) {
  __shared__ float As[64 * 64];
  __shared__ float Ys[64 * 128];
  const int c = blockIdx.x, tid = threadIdx.x;
  const int cg = tid & 31, rg = tid >> 5;
  const int r0 = rg * 4, c0 = cg * 4;

  for (int i = tid; i < 64 * 128; i += 512) {
    int row = i >> 7, col = i & 127;
    Ys[i] = (col == row + 64) ? 1.0f : 0.0f;
  }

  const int t0 = c * LC;
  const float* Ap = A + (size_t)t0 * 4096;
  float4 cA0 = *reinterpret_cast<const float4*>(Ap + tid * 8);
  float4 cA1 = *reinterpret_cast<const float4*>(Ap + tid * 8 + 4);
  float4 bsv = *reinterpret_cast<const float4*>(Bst + t0 * 64 + r0);
  float4 inv = make_float4(0.f, 0.f, 0.f, 0.f);
  if (cg < 16) inv = *reinterpret_cast<const float4*>(inp + t0 * 64 + c0);
  *reinterpret_cast<float4*>(&As[tid * 8])     = cA0;
  *reinterpret_cast<float4*>(&As[tid * 8 + 4]) = cA1;
  __syncthreads();

  for (int s = 0; s < LC; ++s) {
    const int t = t0 + s;
    float4 nA0, nA1, nbs, ninv;
    if (s + 1 < LC) {
      const float* Ap2 = A + (size_t)(t + 1) * 4096;
      nA0 = *reinterpret_cast<const float4*>(Ap2 + tid * 8);
      nA1 = *reinterpret_cast<const float4*>(Ap2 + tid * 8 + 4);
      nbs = *reinterpret_cast<const float4*>(Bst + (t + 1) * 64 + r0);
      ninv = make_float4(0.f, 0.f, 0.f, 0.f);
      if (cg < 16) ninv = *reinterpret_cast<const float4*>(inp + (t + 1) * 64 + c0);
    }

    float bs[4] = {bsv.x, bsv.y, bsv.z, bsv.w};
    float iv[4] = {inv.x, inv.y, inv.z, inv.w};
    float acc[4][4];
#pragma unroll
    for (int i = 0; i < 4; ++i)
#pragma unroll
      for (int j = 0; j < 4; ++j)
        acc[i][j] = (cg < 16) ? bs[i] * iv[j] : 0.0f;

    gemm64<128, 4>(As, Ys, acc, r0, c0);
    __syncthreads();

    if (s + 1 < LC) {
      *reinterpret_cast<float4*>(&As[tid * 8])     = nA0;
      *reinterpret_cast<float4*>(&As[tid * 8 + 4]) = nA1;
      bsv = nbs; inv = ninv;
    }
#pragma unroll
    for (int i = 0; i < 4; ++i) {
      float4 v = make_float4(acc[i][0], acc[i][1], acc[i][2], acc[i][3]);
      *reinterpret_cast<float4*>(&Ys[(r0 + i) * 128 + c0]) = v;
      *reinterpret_cast<float4*>(&g_Y[((size_t)t * 64 + r0 + i) * 128 + c0]) = v;
    }
    __syncthreads();
  }
}

// ---------------- Scan init: gather chunk-final Y into g_S -------------------
__global__ __launch_bounds__(512) void k_scan_init() {
  const int c = blockIdx.x, tid = threadIdx.x;
  const size_t src = ((size_t)(c * LC + LC - 1)) * 64 * 128;
  const size_t dst = (size_t)c * 64 * 128;
#pragma unroll
  for (int i = 0; i < 4; ++i) {
    int idx = (tid + i * 512) * 4;
    *reinterpret_cast<float4*>(&g_S[dst + idx]) =
        *reinterpret_cast<const float4*>(&g_Y[src + idx]);
  }
}

// ---------------- Scan level: S'_c = (P_c P_{c-d}, P_c E_{c-d} + E_c) --------
__global__ __launch_bounds__(512) void k_scan_level(int d, int pp) {
  const float* src = pp ? g_S2 : g_S;
  float*       dst = pp ? g_S  : g_S2;
  const int c = blockIdx.x, tid = threadIdx.x;
  const size_t base  = (size_t)c * 64 * 128;

  if (c < d) {  // copy through
#pragma unroll
    for (int i = 0; i < 4; ++i) {
      int idx = (tid + i * 512) * 4;
      *reinterpret_cast<float4*>(&dst[base + idx]) =
          *reinterpret_cast<const float4*>(&src[base + idx]);
    }
    return;
  }

  __shared__ float As[64 * 64];    // P_c
  __shared__ float Ys[64 * 128];   // Y_{c-d}
  const size_t prev = (size_t)(c - d) * 64 * 128;
  const int cg = tid & 31, rg = tid >> 5;
  const int r0 = rg * 4, c0 = cg * 4;

  {
    int i = tid * 8;                        // As linear index
    int row = i >> 6, k = i & 63;
    *reinterpret_cast<float4*>(&As[i]) =
        *reinterpret_cast<const float4*>(&src[base + (size_t)row * 128 + 64 + k]);
    *reinterpret_cast<float4*>(&As[i + 4]) =
        *reinterpret_cast<const float4*>(&src[base + (size_t)row * 128 + 64 + k + 4]);
  }
#pragma unroll
  for (int i = 0; i < 4; ++i) {
    int idx = (tid + i * 512) * 4;
    *reinterpret_cast<float4*>(&Ys[idx]) =
        *reinterpret_cast<const float4*>(&src[prev + idx]);
  }
  __syncthreads();

  float acc[4][4];
#pragma unroll
  for (int i = 0; i < 4; ++i) {
    if (cg < 16) {  // E_c added on batch cols
      float4 e = *reinterpret_cast<const float4*>(
          &src[base + (size_t)(r0 + i) * 128 + c0]);
      acc[i][0] = e.x; acc[i][1] = e.y; acc[i][2] = e.z; acc[i][3] = e.w;
    } else {
      acc[i][0] = acc[i][1] = acc[i][2] = acc[i][3] = 0.f;
    }
  }
  gemm64<128, 4>(As, Ys, acc, r0, c0);
#pragma unroll
  for (int i = 0; i < 4; ++i)
    *reinterpret_cast<float4*>(&dst[base + (size_t)(r0 + i) * 128 + c0]) =
        make_float4(acc[i][0], acc[i][1], acc[i][2], acc[i][3]);
}

// ---------------- Fixup: out[t] = Xloc[t] + Ploc[t] @ carry[c-1] -------------
// out layout (L,B,N): out[t*4096 + b*64 + n]
__global__ __launch_bounds__(512) void k_fixup(float* __restrict__ out) {
  __shared__ float As[64 * 64];   // Ploc[t]
  __shared__ float Ys[64 * 64];   // carry state (N x B)
  const int t = blockIdx.x, tid = threadIdx.x;
  const int c = t >> 5;
  const int cg = tid & 31, rg = tid >> 5;
  const int r0 = rg * 4, c0 = cg * 2;
  const size_t yb = (size_t)t * 64 * 128;

  float acc[4][2];
#pragma unroll
  for (int i = 0; i < 4; ++i) {
    float2 x = *reinterpret_cast<const float2*>(&g_Y[yb + (size_t)(r0 + i) * 128 + c0]);
    acc[i][0] = x.x; acc[i][1] = x.y;
  }

  if (c > 0) {
    const size_t sb = (size_t)(c - 1) * 64 * 128;  // inclusive scan result (g_S2)
    {
      int i = tid * 8;
      int row = i >> 6, k = i & 63;
      *reinterpret_cast<float4*>(&As[i]) =
          *reinterpret_cast<const float4*>(&g_Y[yb + (size_t)row * 128 + 64 + k]);
      *reinterpret_cast<float4*>(&As[i + 4]) =
          *reinterpret_cast<const float4*>(&g_Y[yb + (size_t)row * 128 + 64 + k + 4]);
    }
#pragma unroll
    for (int i = 0; i < 2; ++i) {
      int idx = tid + i * 512;            // 1024 float4 rows-of-16
      int row = idx >> 4, col = (idx & 15) * 4;
      *reinterpret_cast<float4*>(&Ys[row * 64 + col]) =
          *reinterpret_cast<const float4*>(&g_S2[sb + (size_t)row * 128 + col]);
    }
    __syncthreads();
    gemm64<64, 2>(As, Ys, acc, r0, c0);
  }

  // transposed store: acc[i][j] = x[n=r0+i][b=c0+j] -> out[t][b][n]
#pragma unroll
  for (int j = 0; j < 2; ++j) {
    float4 v = make_float4(acc[0][j], acc[1][j], acc[2][j], acc[3][j]);
    *reinterpret_cast<float4*>(&out[(size_t)t * 4096 + (size_t)(c0 + j) * 64 + r0]) = v;
  }
}

extern "C" void kernel_launch(void* const* d_in, const int* in_sizes, int n_in,
                              void* d_out, int out_size) {
  const float* inp = (const float*)d_in[0];   // (L, B)
  const float* A   = (const float*)d_in[1];   // (L, N, N)
  const float* Bst = (const float*)d_in[2];   // (L, N)
  float* out = (float*)d_out;

  k_phase1<<<NCHUNK, 512>>>(inp, A, Bst);
  k_scan_init<<<NCHUNK, 512>>>();
  int pp = 0;
  for (int d = 1; d < NCHUNK; d <<= 1) {      // 7 levels; final result in g_S2
    k_scan_level<<<NCHUNK, 512>>>(d, pp);
    pp ^= 1;
  }
  k_fixup<<<LTOT, 512>>>(out);
}

// round 3
// speedup vs baseline: 1.0037x; 1.0037x over previous
#include <cuda_runtime.h>

#define LTOT   4096
#define NST    64
#define BSZ    64
#define NCHUNK 128
#define LC     32

// Scratch (__device__ globals — no allocation allowed).
// g_Y[t][row n][col]: col 0..63 = Xloc (batch cols), col 64..127 = Ploc.
__device__ float g_Y [LTOT * 64 * 128];     // 128 MB
__device__ float g_S [NCHUNK * 64 * 128];   // scan ping
__device__ float g_S2[NCHUNK * 64 * 128];   // scan pong

// (64xW) += (64x64 As) @ (64xW Ys); thread owns 4 rows x TN cols.
template<int W, int TN>
__device__ __forceinline__ void gemm64(const float* __restrict__ As,
                                       const float* __restrict__ Ys,
                                       float acc[4][TN], int r0, int c0) {
#pragma unroll 4
  for (int k0 = 0; k0 < 64; k0 += 4) {
    float a[4][4];
#pragma unroll
    for (int i = 0; i < 4; ++i) {
      float4 av = *reinterpret_cast<const float4*>(&As[(r0 + i) * 64 + k0]);
      a[i][0] = av.x; a[i][1] = av.y; a[i][2] = av.z; a[i][3] = av.w;
    }
#pragma unroll
    for (int kk = 0; kk < 4; ++kk) {
      float y[TN];
      if constexpr (TN == 4) {
        float4 yv = *reinterpret_cast<const float4*>(&Ys[(k0 + kk) * W + c0]);
        y[0] = yv.x; y[1] = yv.y; y[2] = yv.z; y[3] = yv.w;
      } else {
        float2 yv = *reinterpret_cast<const float2*>(&Ys[(k0 + kk) * W + c0]);
        y[0] = yv.x; y[1] = yv.y;
      }
#pragma unroll
      for (int i = 0; i < 4; ++i)
#pragma unroll
        for (int j = 0; j < TN; ++j)
          acc[i][j] += a[i][kk] * y[j];
    }
  }
}

// ---------------- Phase 1: per-chunk joint recurrence, store every step ------
__global__ __launch_bounds__(512) void k_phase1(const float* __restrict__ inp,
                                                const float* __restrict__ A,
                                                const float* __restrict__ Bst) {
  __shared__ float As[64 * 64];
  __shared__ float Ys[64 * 128];
  const int c = blockIdx.x, tid = threadIdx.x;
  const int cg = tid & 31, rg = tid >> 5;
  const int r0 = rg * 4, c0 = cg * 4;

  for (int i = tid; i < 64 * 128; i += 512) {
    int row = i >> 7, col = i & 127;
    Ys[i] = (col == row + 64) ? 1.0f : 0.0f;
  }

  const int t0 = c * LC;
  const float* Ap = A + (size_t)t0 * 4096;
  float4 cA0 = *reinterpret_cast<const float4*>(Ap + tid * 8);
  float4 cA1 = *reinterpret_cast<const float4*>(Ap + tid * 8 + 4);
  float4 bsv = *reinterpret_cast<const float4*>(Bst + t0 * 64 + r0);
  float4 inv = make_float4(0.f, 0.f, 0.f, 0.f);
  if (cg < 16) inv = *reinterpret_cast<const float4*>(inp + t0 * 64 + c0);
  *reinterpret_cast<float4*>(&As[tid * 8])     = cA0;
  *reinterpret_cast<float4*>(&As[tid * 8 + 4]) = cA1;
  __syncthreads();

  for (int s = 0; s < LC; ++s) {
    const int t = t0 + s;
    float4 nA0, nA1, nbs, ninv;
    if (s + 1 < LC) {
      const float* Ap2 = A + (size_t)(t + 1) * 4096;
      nA0 = *reinterpret_cast<const float4*>(Ap2 + tid * 8);
      nA1 = *reinterpret_cast<const float4*>(Ap2 + tid * 8 + 4);
      nbs = *reinterpret_cast<const float4*>(Bst + (t + 1) * 64 + r0);
      ninv = make_float4(0.f, 0.f, 0.f, 0.f);
      if (cg < 16) ninv = *reinterpret_cast<const float4*>(inp + (t + 1) * 64 + c0);
    }

    float bs[4] = {bsv.x, bsv.y, bsv.z, bsv.w};
    float iv[4] = {inv.x, inv.y, inv.z, inv.w};
    float acc[4][4];
#pragma unroll
    for (int i = 0; i < 4; ++i)
#pragma unroll
      for (int j = 0; j < 4; ++j)
        acc[i][j] = (cg < 16) ? bs[i] * iv[j] : 0.0f;

    gemm64<128, 4>(As, Ys, acc, r0, c0);
    __syncthreads();

    if (s + 1 < LC) {
      *reinterpret_cast<float4*>(&As[tid * 8])     = nA0;
      *reinterpret_cast<float4*>(&As[tid * 8 + 4]) = nA1;
      bsv = nbs; inv = ninv;
    }
#pragma unroll
    for (int i = 0; i < 4; ++i) {
      float4 v = make_float4(acc[i][0], acc[i][1], acc[i][2], acc[i][3]);
      *reinterpret_cast<float4*>(&Ys[(r0 + i) * 128 + c0]) = v;
      *reinterpret_cast<float4*>(&g_Y[((size_t)t * 64 + r0 + i) * 128 + c0]) = v;
    }
    __syncthreads();
  }
}

// ---------------- Scan init: gather chunk-final Y into g_S -------------------
__global__ __launch_bounds__(512) void k_scan_init() {
  const int c = blockIdx.x, tid = threadIdx.x;
  const size_t src = ((size_t)(c * LC + LC - 1)) * 64 * 128;
  const size_t dst = (size_t)c * 64 * 128;
#pragma unroll
  for (int i = 0; i < 4; ++i) {
    int idx = (tid + i * 512) * 4;
    *reinterpret_cast<float4*>(&g_S[dst + idx]) =
        *reinterpret_cast<const float4*>(&g_Y[src + idx]);
  }
}

// ---------------- Scan level: S'_c = (P_c P_{c-d}, P_c E_{c-d} + E_c) --------
__global__ __launch_bounds__(512) void k_scan_level(int d, int pp) {
  const float* src = pp ? g_S2 : g_S;
  float*       dst = pp ? g_S  : g_S2;
  const int c = blockIdx.x, tid = threadIdx.x;
  const size_t base  = (size_t)c * 64 * 128;

  if (c < d) {  // copy through
#pragma unroll
    for (int i = 0; i < 4; ++i) {
      int idx = (tid + i * 512) * 4;
      *reinterpret_cast<float4*>(&dst[base + idx]) =
          *reinterpret_cast<const float4*>(&src[base + idx]);
    }
    return;
  }

  __shared__ float As[64 * 64];    // P_c
  __shared__ float Ys[64 * 128];   // Y_{c-d}
  const size_t prev = (size_t)(c - d) * 64 * 128;
  const int cg = tid & 31, rg = tid >> 5;
  const int r0 = rg * 4, c0 = cg * 4;

  {
    int i = tid * 8;                        // As linear index
    int row = i >> 6, k = i & 63;
    *reinterpret_cast<float4*>(&As[i]) =
        *reinterpret_cast<const float4*>(&src[base + (size_t)row * 128 + 64 + k]);
    *reinterpret_cast<float4*>(&As[i + 4]) =
        *reinterpret_cast<const float4*>(&src[base + (size_t)row * 128 + 64 + k + 4]);
  }
#pragma unroll
  for (int i = 0; i < 4; ++i) {
    int idx = (tid + i * 512) * 4;
    *reinterpret_cast<float4*>(&Ys[idx]) =
        *reinterpret_cast<const float4*>(&src[prev + idx]);
  }
  __syncthreads();

  float acc[4][4];
#pragma unroll
  for (int i = 0; i < 4; ++i) {
    if (cg < 16) {  // E_c added on batch cols
      float4 e = *reinterpret_cast<const float4*>(
          &src[base + (size_t)(r0 + i) * 128 + c0]);
      acc[i][0] = e.x; acc[i][1] = e.y; acc[i][2] = e.z; acc[i][3] = e.w;
    } else {
      acc[i][0] = acc[i][1] = acc[i][2] = acc[i][3] = 0.f;
    }
  }
  gemm64<128, 4>(As, Ys, acc, r0, c0);
#pragma unroll
  for (int i = 0; i < 4; ++i)
    *reinterpret_cast<float4*>(&dst[base + (size_t)(r0 + i) * 128 + c0]) =
        make_float4(acc[i][0], acc[i][1], acc[i][2], acc[i][3]);
}

// ---------------- Fixup: out[t] = Xloc[t] + Ploc[t] @ carry[c-1] -------------
// out layout (L,B,N): out[t*4096 + b*64 + n]
__global__ __launch_bounds__(512) void k_fixup(float* __restrict__ out) {
  __shared__ float As[64 * 64];   // Ploc[t]
  __shared__ float Ys[64 * 64];   // carry state (N x B)
  const int t = blockIdx.x, tid = threadIdx.x;
  const int c = t >> 5;
  const int cg = tid & 31, rg = tid >> 5;
  const int r0 = rg * 4, c0 = cg * 2;
  const size_t yb = (size_t)t * 64 * 128;

  float acc[4][2];
#pragma unroll
  for (int i = 0; i < 4; ++i) {
    float2 x = *reinterpret_cast<const float2*>(&g_Y[yb + (size_t)(r0 + i) * 128 + c0]);
    acc[i][0] = x.x; acc[i][1] = x.y;
  }

  if (c > 0) {
    const size_t sb = (size_t)(c - 1) * 64 * 128;  // inclusive scan result (g_S2)
    {
      int i = tid * 8;
      int row = i >> 6, k = i & 63;
      *reinterpret_cast<float4*>(&As[i]) =
          *reinterpret_cast<const float4*>(&g_Y[yb + (size_t)row * 128 + 64 + k]);
      *reinterpret_cast<float4*>(&As[i + 4]) =
          *reinterpret_cast<const float4*>(&g_Y[yb + (size_t)row * 128 + 64 + k + 4]);
    }
#pragma unroll
    for (int i = 0; i < 2; ++i) {
      int idx = tid + i * 512;            // 1024 float4 rows-of-16
      int row = idx >> 4, col = (idx & 15) * 4;
      *reinterpret_cast<float4*>(&Ys[row * 64 + col]) =
          *reinterpret_cast<const float4*>(&g_S2[sb + (size_t)row * 128 + col]);
    }
    __syncthreads();
    gemm64<64, 2>(As, Ys, acc, r0, c0);
  }

  // transposed store: acc[i][j] = x[n=r0+i][b=c0+j] -> out[t][b][n]
#pragma unroll
  for (int j = 0; j < 2; ++j) {
    float4 v = make_float4(acc[0][j], acc[1][j], acc[2][j], acc[3][j]);
    *reinterpret_cast<float4*>(&out[(size_t)t * 4096 + (size_t)(c0 + j) * 64 + r0]) = v;
  }
}

extern "C" void kernel_launch(void* const* d_in, const int* in_sizes, int n_in,
                              void* d_out, int out_size) {
  const float* inp = (const float*)d_in[0];   // (L, B)
  const float* A   = (const float*)d_in[1];   // (L, N, N)
  const float* Bst = (const float*)d_in[2];   // (L, N)
  float* out = (float*)d_out;

  k_phase1<<<NCHUNK, 512>>>(inp, A, Bst);
  k_scan_init<<<NCHUNK, 512>>>();
  int pp = 0;
  for (int d = 1; d < NCHUNK; d <<= 1) {      // 7 levels; final result in g_S2
    k_scan_level<<<NCHUNK, 512>>>(d, pp);
    pp ^= 1;
  }
  k_fixup<<<LTOT, 512>>>(out);
}